// round 6
// baseline (speedup 1.0000x reference)
#include <cuda_runtime.h>
#include <cstdint>

#define CAND 2048          // candidate buffer entries (u64)
#define TBL  2048          // bins per table
#define XSCALE 102.4f      // TBL / 20  (range [-10, 10])
#define XOFF   1024.0f     // 10 * XSCALE

static __device__ float g_rowsum[8192];
static __device__ float g_table[2 * TBL];   // [0..TBL) = f_neg, [TBL..2TBL) = f_pos
static __device__ int   g_count = 0;

// ---------------------------------------------------------------------------
// sortable-float key helpers
// ---------------------------------------------------------------------------
__device__ __forceinline__ unsigned sortkey32(float x) {
    unsigned u = __float_as_uint(x);
    return u ^ ((unsigned)(((int)u) >> 31) | 0x80000000u);
}
__device__ __forceinline__ unsigned long long makekey(unsigned k32, int c) {
    return ((unsigned long long)k32 << 32) |
           (unsigned long long)(0xFFFFFFFFu - (unsigned)c);
}

// ---------------------------------------------------------------------------
// Kernel 0: build the per-element loss tables once (exact math).
//   f_neg(x) = ln(max(min(1.05-sigmoid,1),eps)) * (1-pv)^4
//   f_pos(x) = ln(max(sigmoid,eps)) * (1-sigmoid)
// ---------------------------------------------------------------------------
__global__ void asl_build_table()
{
    int j = blockIdx.x * 256 + threadIdx.x;           // 0 .. 2*TBL-1
    bool pos = j >= TBL;
    int  q   = pos ? j - TBL : j;
    float x  = (q + 0.5f) * (20.0f / TBL) - 10.0f;    // bin center
    float sp = 1.0f / (1.0f + expf(-x));
    float v;
    if (pos) {
        v = logf(fmaxf(sp, 1e-8f)) * (1.0f - sp);
    } else {
        float pv = fminf(1.05f - sp, 1.0f);
        float om = 1.0f - pv;
        float om2 = om * om;
        v = logf(fmaxf(pv, 1e-8f)) * om2 * om2;
    }
    g_table[j] = v;
}

// ---------------------------------------------------------------------------
// per-element work: table lookup + whitelist flags
// ---------------------------------------------------------------------------
__device__ __forceinline__ void process_elem(float xv, float yv, int c,
                                             const int* __restrict__ cat,
                                             const float* __restrict__ s_tbl,
                                             float& sum, int& flags)
{
    bool pos = (yv != 0.0f);
    float fx = fmaf(xv, XSCALE, XOFF);
    int j = (int)fx;
    j = min(max(j, 0), TBL - 1);
    sum += s_tbl[j + (pos ? TBL : 0)];
    if (pos) {
        int cv = __ldg(&cat[c]);
        flags |= (1 << (cv - 1)) & 7;   // bits for cat 1/2/3; cat 4 -> 0
    }
}

// ---------------------------------------------------------------------------
// Kernel 1: one block per row. Threshold-prefilter top-10 + table-based sum.
// ---------------------------------------------------------------------------
__global__ void __launch_bounds__(256)
asl_row_kernel(const float* __restrict__ X,
               const float* __restrict__ Y,
               const int*   __restrict__ cat,
               const unsigned char* __restrict__ inmap,
               int C, int B, float* __restrict__ out)
{
    const int row  = blockIdx.x;
    const int tid  = threadIdx.x;
    const int lane = tid & 31;
    const int warp = tid >> 5;
    const unsigned FULL = 0xFFFFFFFFu;

    const float* __restrict__ xr = X + (size_t)row * C;
    const float* __restrict__ yr = Y + (size_t)row * C;

    __shared__ float s_tbl[2 * TBL];                  // 16 KB
    __shared__ unsigned long long s_buf[CAND];        // 16 KB
    __shared__ unsigned long long s_red[8];
    __shared__ unsigned long long s_win;
    __shared__ unsigned long long s_top[10];
    __shared__ float s_sumw[8];
    __shared__ int s_flags, s_cnt, s_last;

    // copy tables L2 -> smem (float4)
    {
        const float4* gt = (const float4*)g_table;
        float4* st = (float4*)s_tbl;
        for (int i = tid; i < (2 * TBL) / 4; i += 256) st[i] = gt[i];
    }
    if (tid == 0) { s_flags = 0; s_cnt = 10; }
    __syncthreads();

    float sum = 0.0f;
    int flags = 0;

    // ---- bootstrap: chunk 0 (elements 0..255): math + exact block top-10 ----
    unsigned long long mykey = 0ULL;
    if (tid < C) {
        float xv = xr[tid], yv = yr[tid];
        process_elem(xv, yv, tid, cat, s_tbl, sum, flags);
        mykey = makekey(sortkey32(xv), tid);
    }
    for (int k = 0; k < 10; ++k) {
        unsigned long long v = mykey;
#pragma unroll
        for (int off = 16; off; off >>= 1) {
            unsigned long long o = __shfl_down_sync(FULL, v, off);
            if (o > v) v = o;
        }
        if (lane == 0) s_red[warp] = v;
        __syncthreads();
        if (warp == 0) {
            unsigned long long v2 = (lane < 8) ? s_red[lane] : 0ULL;
#pragma unroll
            for (int off = 4; off; off >>= 1) {
                unsigned long long o = __shfl_down_sync(FULL, v2, off);
                if (o > v2) v2 = o;
            }
            if (lane == 0) { s_win = v2; s_buf[k] = v2; }
        }
        __syncthreads();
        if (mykey == s_win) mykey = 0ULL;
    }

    const unsigned long long thr = s_buf[9];
    const unsigned thr32 = (unsigned)(thr >> 32);

    // ---- main streaming loop: table sum + candidate collection ----
#pragma unroll 4
    for (int c = 256 + tid; c < C; c += 256) {
        float xv = xr[c], yv = yr[c];
        process_elem(xv, yv, c, cat, s_tbl, sum, flags);
        unsigned ux = sortkey32(xv);
        if (ux >= thr32) {
            unsigned long long key = makekey(ux, c);
            if (key > thr) {
                int p = atomicAdd(&s_cnt, 1);
                if (p < CAND) s_buf[p] = key;
            }
        }
    }

    // ---- reduce sum & flags ----
#pragma unroll
    for (int off = 16; off; off >>= 1) {
        sum   += __shfl_down_sync(FULL, sum, off);
        flags |= __shfl_down_sync(FULL, flags, off);
    }
    if (lane == 0) { s_sumw[warp] = sum; atomicOr(&s_flags, flags); }
    __syncthreads();

    // ---- extract exact block top-10 from candidate buffer ----
    for (;;) {
        int n = min(s_cnt, CAND);
        bool over = s_cnt > CAND;

        unsigned long long loc[8];
#pragma unroll
        for (int t = 0; t < 8; ++t) {
            int i = tid + (t << 8);
            loc[t] = (i < n) ? s_buf[i] : 0ULL;
        }
        for (int k = 0; k < 10; ++k) {
            unsigned long long v = 0ULL;
#pragma unroll
            for (int t = 0; t < 8; ++t) if (loc[t] > v) v = loc[t];
#pragma unroll
            for (int off = 16; off; off >>= 1) {
                unsigned long long o = __shfl_down_sync(FULL, v, off);
                if (o > v) v = o;
            }
            if (lane == 0) s_red[warp] = v;
            __syncthreads();
            if (warp == 0) {
                unsigned long long v2 = (lane < 8) ? s_red[lane] : 0ULL;
#pragma unroll
                for (int off = 4; off; off >>= 1) {
                    unsigned long long o = __shfl_down_sync(FULL, v2, off);
                    if (o > v2) v2 = o;
                }
                if (lane == 0) { s_win = v2; s_top[k] = v2; }
            }
            __syncthreads();
#pragma unroll
            for (int t = 0; t < 8; ++t) if (loc[t] == s_win) loc[t] = 0ULL;
        }
        if (!over) break;

        // fallback (effectively unreachable for this data): raise threshold,
        // recollect all elements with key >= new threshold. Terminates since
        // the threshold strictly increases each pass.
        __syncthreads();
        if (tid == 0) s_cnt = 0;
        unsigned long long th2 = s_top[9];
        unsigned th2h = (unsigned)(th2 >> 32);
        __syncthreads();
        for (int c = tid; c < C; c += 256) {
            unsigned ux = sortkey32(xr[c]);
            if (ux >= th2h) {
                unsigned long long key = makekey(ux, c);
                if (key >= th2) {
                    int p = atomicAdd(&s_cnt, 1);
                    if (p < CAND) s_buf[p] = key;
                }
            }
        }
        __syncthreads();
    }

    // ---- correction for the top-10 elements (exact math) ----
    const int fl = s_flags;
    const bool p1 = (fl & 1) != 0, p2 = (fl & 2) != 0, p3 = (fl & 4) != 0;
    const bool has4 = !(p1 | p2 | p3);

    float delta = 0.0f;
    if (tid < 10) {
        const unsigned idx = 0xFFFFFFFFu - (unsigned)(s_top[tid] & 0xFFFFFFFFull);
        const float xv = xr[idx];
        const float yv = yr[idx];
        const float sp = __fdividef(1.0f, 1.0f + __expf(-xv));
        const float sn = fminf(1.05f - sp, 1.0f);
        const bool  pos = (yv != 0.0f);
        const float pv  = pos ? sp : sn;
        const float l   = __logf(fmaxf(pv, 1e-8f));
        const float om  = 1.0f - pv;
        const float om2 = om * om;
        const float w   = pos ? om : om2 * om2;

        const int  cv  = cat[idx];
        const bool inm = inmap[idx] != 0;
        const bool condA = (!inm) && has4;
        const bool condB = (cv == 1 && p1) || (cv == 2 && p2) ||
                           (cv == 3 && p3) || (cv == 4 && has4);
        if (condA || condB) {
            const float factor = (pos ? sn : sp) * 2.0f;  // ALPHA3 = 2
            delta = l * w * (factor - 1.0f);
        }
    }
    if (warp == 0) {
#pragma unroll
        for (int off = 16; off; off >>= 1)
            delta += __shfl_down_sync(FULL, delta, off);
    }
    if (tid == 0) {
        float tot = delta;
#pragma unroll
        for (int i = 0; i < 8; ++i) tot += s_sumw[i];
        g_rowsum[row] = tot;
    }

    // ---- last-block finalize: deterministic double reduction ----
    __threadfence();
    if (tid == 0) s_last = (atomicAdd(&g_count, 1) == gridDim.x - 1) ? 1 : 0;
    __syncthreads();
    if (s_last) {
        __threadfence();
        double* sd = (double*)s_buf;
        double acc = 0.0;
        for (int i = tid; i < B; i += 256) acc += (double)g_rowsum[i];
        sd[tid] = acc;
        __syncthreads();
#pragma unroll
        for (int off = 128; off; off >>= 1) {
            if (tid < off) sd[tid] += sd[tid + off];
            __syncthreads();
        }
        if (tid == 0) { out[0] = -(float)sd[0]; g_count = 0; }
    }
}

extern "C" void kernel_launch(void* const* d_in, const int* in_sizes, int n_in,
                              void* d_out, int out_size)
{
    const float*         X   = (const float*)d_in[0];
    const float*         Y   = (const float*)d_in[1];
    const int*           cat = (const int*)d_in[2];
    const unsigned char* inm = (const unsigned char*)d_in[3];

    const int C = in_sizes[2];        // per-class arrays -> 9605
    const int B = in_sizes[0] / C;    // 2048

    asl_build_table<<<(2 * TBL) / 256, 256>>>();
    asl_row_kernel<<<B, 256>>>(X, Y, cat, inm, C, B, (float*)d_out);
}

// round 7
// speedup vs baseline: 1.9436x; 1.9436x over previous
#include <cuda_runtime.h>
#include <cstdint>

#define CAND 512           // candidate buffer entries (u64)
#define TBL  2048          // bins per table
#define XSCALE 102.4f      // TBL / 20  (range [-10, 10])
#define XOFF   1024.0f     // 10 * XSCALE
#define THRESH0 2.7f       // prefilter threshold (fallback makes any value correct)
#define FULLM 0xFFFFFFFFu

static __device__ float g_rowsum[8192];
static __device__ float g_table[2 * TBL];          // [0..TBL)=f_neg, [TBL..2TBL)=f_pos
static __device__ unsigned char g_catbit[16384];   // (1<<(cat-1))&7
static __device__ int   g_count = 0;

// ---------------------------------------------------------------------------
__device__ __forceinline__ unsigned sortkey32(float x) {
    unsigned u = __float_as_uint(x);
    return u ^ ((unsigned)(((int)u) >> 31) | 0x80000000u);
}
__device__ __forceinline__ unsigned long long makekey(unsigned k32, int c) {
    return ((unsigned long long)k32 << 32) |
           (unsigned long long)(0xFFFFFFFFu - (unsigned)c);
}

// ---------------------------------------------------------------------------
// Kernel 0: build loss tables (exact math) + catbit LUT.
// ---------------------------------------------------------------------------
__global__ void asl_build(const int* __restrict__ cat, int C)
{
    int j = blockIdx.x * 256 + threadIdx.x;
    if (j < 2 * TBL) {
        bool pos = j >= TBL;
        int  q   = pos ? j - TBL : j;
        float x  = (q + 0.5f) * (20.0f / TBL) - 10.0f;
        float sp = 1.0f / (1.0f + expf(-x));
        float v;
        if (pos) {
            v = logf(fmaxf(sp, 1e-8f)) * (1.0f - sp);
        } else {
            float pv = fminf(1.05f - sp, 1.0f);
            float om = 1.0f - pv;
            float om2 = om * om;
            v = logf(fmaxf(pv, 1e-8f)) * om2 * om2;
        }
        g_table[j] = v;
    }
    int c = j - 2 * TBL;
    if (c >= 0 && c < C)
        g_catbit[c] = (unsigned char)((1 << (cat[c] - 1)) & 7);
}

// ---------------------------------------------------------------------------
__device__ __forceinline__ float tbl_val(float xv, float yv,
                                         const float* __restrict__ s_tbl)
{
    float fx = fmaf(xv, XSCALE, XOFF);
    fx = fminf(fx, 2047.0f);
    fx = fmaxf(fx, 0.0f);
    int j = (int)fx;
    return s_tbl[j + ((yv != 0.0f) ? TBL : 0)];
}

__device__ __forceinline__ void collect(float xv, int c,
                                        int* s_cnt, unsigned long long* s_buf)
{
    unsigned long long key = makekey(sortkey32(xv), c);
    int q = atomicAdd(s_cnt, 1);
    if (q < CAND) s_buf[q] = key;
}

// warp-0-only: exact top-10 of s_buf[0..m), zeroing winners as it goes
__device__ __forceinline__ void extract10(unsigned long long* s_buf, int m,
                                          unsigned long long* s_top, int lane)
{
    for (int k = 0; k < 10; ++k) {
        unsigned long long v = 0ULL;
        for (int i = lane; i < m; i += 32) {
            unsigned long long b = s_buf[i];
            if (b > v) v = b;
        }
#pragma unroll
        for (int off = 16; off; off >>= 1) {
            unsigned long long o = __shfl_down_sync(FULLM, v, off);
            if (o > v) v = o;
        }
        unsigned long long w = __shfl_sync(FULLM, v, 0);
        if (lane == 0) s_top[k] = w;
        for (int i = lane; i < m; i += 32)
            if (s_buf[i] == w) s_buf[i] = 0ULL;
    }
}

// ---------------------------------------------------------------------------
// Kernel 1: one block per row.
// ---------------------------------------------------------------------------
__global__ void __launch_bounds__(256, 8)
asl_row_kernel(const float* __restrict__ X,
               const float* __restrict__ Y,
               const int*   __restrict__ cat,
               const unsigned char* __restrict__ inmap,
               int C, int B, float* __restrict__ out)
{
    const int row  = blockIdx.x;
    const int tid  = threadIdx.x;
    const int lane = tid & 31;
    const int warp = tid >> 5;

    const float* __restrict__ xr = X + (size_t)row * C;
    const float* __restrict__ yr = Y + (size_t)row * C;

    __shared__ float s_tbl[2 * TBL];              // 16 KB
    __shared__ unsigned long long s_buf[CAND];    // 4 KB
    __shared__ unsigned long long s_top[10];
    __shared__ float s_sumw[8];
    __shared__ int s_flags, s_cnt, s_last;

    {   // table L2 -> smem
        const float4* gt = (const float4*)g_table;
        float4* st = (float4*)s_tbl;
#pragma unroll
        for (int i = tid; i < (2 * TBL) / 4; i += 256) st[i] = gt[i];
    }
    if (tid == 0) { s_flags = 0; s_cnt = 0; }
    __syncthreads();

    float sum = 0.0f;
    int flags = 0;

    // alignment: first element index whose address is 16B aligned
    const int p = (int)((4 - (((size_t)row * (size_t)C) & 3)) & 3);
    const int nv = (C - p) >> 2;
    const int t0 = p + (nv << 2);

    // prologue + tail (<=3 elements each)
    for (int c = tid; c < p; c += 256) {
        float xv = xr[c], yv = yr[c];
        sum += tbl_val(xv, yv, s_tbl);
        if (yv != 0.0f) flags |= g_catbit[c];
        if (xv > THRESH0) collect(xv, c, &s_cnt, s_buf);
    }
    for (int c = t0 + tid; c < C; c += 256) {
        float xv = xr[c], yv = yr[c];
        sum += tbl_val(xv, yv, s_tbl);
        if (yv != 0.0f) flags |= g_catbit[c];
        if (xv > THRESH0) collect(xv, c, &s_cnt, s_buf);
    }

    // ---- main vectorized streaming loop ----
    const float4* __restrict__ x4 = (const float4*)(xr + p);
    const float4* __restrict__ y4 = (const float4*)(yr + p);
    for (int v = tid; v < nv; v += 256) {
        const float4 xq = x4[v];
        const float4 yq = y4[v];

        sum += tbl_val(xq.x, yq.x, s_tbl);
        sum += tbl_val(xq.y, yq.y, s_tbl);
        sum += tbl_val(xq.z, yq.z, s_tbl);
        sum += tbl_val(xq.w, yq.w, s_tbl);

        const float xm = fmaxf(fmaxf(xq.x, xq.y), fmaxf(xq.z, xq.w));
        if (xm > THRESH0) {
            const int cb = p + (v << 2);
            if (xq.x > THRESH0) collect(xq.x, cb + 0, &s_cnt, s_buf);
            if (xq.y > THRESH0) collect(xq.y, cb + 1, &s_cnt, s_buf);
            if (xq.z > THRESH0) collect(xq.z, cb + 2, &s_cnt, s_buf);
            if (xq.w > THRESH0) collect(xq.w, cb + 3, &s_cnt, s_buf);
        }
        const float ym = fmaxf(fmaxf(yq.x, yq.y), fmaxf(yq.z, yq.w));
        if (ym != 0.0f) {
            const int cb = p + (v << 2);
            if (yq.x != 0.0f) flags |= g_catbit[cb + 0];
            if (yq.y != 0.0f) flags |= g_catbit[cb + 1];
            if (yq.z != 0.0f) flags |= g_catbit[cb + 2];
            if (yq.w != 0.0f) flags |= g_catbit[cb + 3];
        }
    }

    // ---- reduce sum & flags ----
#pragma unroll
    for (int off = 16; off; off >>= 1) {
        sum   += __shfl_down_sync(FULLM, sum, off);
        flags |= __shfl_down_sync(FULLM, flags, off);
    }
    if (lane == 0) { s_sumw[warp] = sum; atomicOr(&s_flags, flags); }
    __syncthreads();

    // ---- resolve exact top-10 (fast path: 10 <= n <= CAND on first try) ----
    float thF = THRESH0;
    unsigned long long thK = 0ULL;
    bool useKey = false;
    int iter = 0;
    for (;;) {
        const int n = s_cnt;
        if ((n >= 10 && n <= CAND) || iter >= 32) {
            if (warp == 0) extract10(s_buf, min(n, CAND), s_top, lane);
            __syncthreads();
            break;
        }
        if (n > CAND) {
            // raise threshold to 10th-largest key of the stored candidates
            if (warp == 0) extract10(s_buf, CAND, s_top, lane);
            __syncthreads();
            thK = s_top[9];
            useKey = true;       // recollect with key >= thK (inclusive, >=10 guaranteed)
        } else {
            thF -= 4.0f;         // too few: lower the float threshold
            useKey = false;
        }
        __syncthreads();
        if (tid == 0) s_cnt = 0;
        __syncthreads();
        for (int c = tid; c < C; c += 256) {
            const float xv = xr[c];
            if (useKey) {
                unsigned long long key = makekey(sortkey32(xv), c);
                if (key >= thK) {
                    int q = atomicAdd(&s_cnt, 1);
                    if (q < CAND) s_buf[q] = key;
                }
            } else if (xv > thF) {
                collect(xv, c, &s_cnt, s_buf);
            }
        }
        __syncthreads();
        ++iter;
    }

    // ---- correction for the top-10 elements (exact math) ----
    const int fl = s_flags;
    const bool p1 = (fl & 1) != 0, p2 = (fl & 2) != 0, p3 = (fl & 4) != 0;
    const bool has4 = !(p1 | p2 | p3);

    float delta = 0.0f;
    if (tid < 10 && s_top[tid] != 0ULL) {
        const unsigned idx = 0xFFFFFFFFu - (unsigned)(s_top[tid] & 0xFFFFFFFFull);
        const float xv = xr[idx];
        const float yv = yr[idx];
        const float sp = __fdividef(1.0f, 1.0f + __expf(-xv));
        const float sn = fminf(1.05f - sp, 1.0f);
        const bool  pos = (yv != 0.0f);
        const float pv  = pos ? sp : sn;
        const float l   = __logf(fmaxf(pv, 1e-8f));
        const float om  = 1.0f - pv;
        const float om2 = om * om;
        const float w   = pos ? om : om2 * om2;

        const int  cv  = cat[idx];
        const bool inm = inmap[idx] != 0;
        const bool condA = (!inm) && has4;
        const bool condB = (cv == 1 && p1) || (cv == 2 && p2) ||
                           (cv == 3 && p3) || (cv == 4 && has4);
        if (condA || condB) {
            const float factor = (pos ? sn : sp) * 2.0f;   // ALPHA3 = 2
            delta = l * w * (factor - 1.0f);
        }
    }
    if (warp == 0) {
#pragma unroll
        for (int off = 16; off; off >>= 1)
            delta += __shfl_down_sync(FULLM, delta, off);
    }
    if (tid == 0) {
        float tot = delta;
#pragma unroll
        for (int i = 0; i < 8; ++i) tot += s_sumw[i];
        g_rowsum[row] = tot;
    }

    // ---- last-block finalize: deterministic double reduction ----
    __threadfence();
    if (tid == 0) s_last = (atomicAdd(&g_count, 1) == gridDim.x - 1) ? 1 : 0;
    __syncthreads();
    if (s_last) {
        __threadfence();
        double* sd = (double*)s_buf;
        double acc = 0.0;
        for (int i = tid; i < B; i += 256) acc += (double)g_rowsum[i];
        sd[tid] = acc;
        __syncthreads();
#pragma unroll
        for (int off = 128; off; off >>= 1) {
            if (tid < off) sd[tid] += sd[tid + off];
            __syncthreads();
        }
        if (tid == 0) { out[0] = -(float)sd[0]; g_count = 0; }
    }
}

extern "C" void kernel_launch(void* const* d_in, const int* in_sizes, int n_in,
                              void* d_out, int out_size)
{
    const float*         X   = (const float*)d_in[0];
    const float*         Y   = (const float*)d_in[1];
    const int*           cat = (const int*)d_in[2];
    const unsigned char* inm = (const unsigned char*)d_in[3];

    const int C = in_sizes[2];        // per-class arrays -> 9605
    const int B = in_sizes[0] / C;    // 2048

    asl_build<<<(2 * TBL + C + 255) / 256, 256>>>(cat, C);
    asl_row_kernel<<<B, 256>>>(X, Y, cat, inm, C, B, (float*)d_out);
}